// round 16
// baseline (speedup 1.0000x reference)
#include <cuda_runtime.h>
#include <cuda_fp16.h>
#include <cstdint>

#define EPSV 1e-5f

// ---------------- scratch (device globals; no allocation allowed) ----------------
__device__ __half g_p1h[8ull * 128 * 128 * 128];  // pooled stage 1 fp16: (B,C,128,128)
__device__ __half g_p2h[8ull * 128 * 64 * 64];    // pooled stage 2 fp16: (B,C,4096)
__device__ float  g_part[8ull * 16 * 128 * 128];  // gram partials: (B, 16 splits, C, C)
__device__ __half g_Sth[8ull * 128 * 128];        // sim transposed fp16: [b][c][k]
__device__ int    g_cnt[8];                       // per-batch arrival counters (self-reset)

// ---------------- kernel 1: dwconv s2 + BN + PReLU, fp32 in -> fp16 out ----------------
__device__ __forceinline__ void load_row9(float* f, const float* rowp, int tx)
{
    float4 A = (tx > 0) ? *(const float4*)(rowp + tx * 8 - 4)
                        : make_float4(0.f, 0.f, 0.f, 0.f);
    float4 B = *(const float4*)(rowp + tx * 8);
    float4 C = *(const float4*)(rowp + tx * 8 + 4);
    f[0] = A.w;
    f[1] = B.x; f[2] = B.y; f[3] = B.z; f[4] = B.w;
    f[5] = C.x; f[6] = C.y; f[7] = C.z; f[8] = C.w;
}

__global__ void dwconv1_kernel(
    const float* __restrict__ in, __half* __restrict__ out,
    const float* __restrict__ w,
    const float* __restrict__ gamma, const float* __restrict__ beta,
    const float* __restrict__ mean, const float* __restrict__ var,
    const float* __restrict__ alpha)
{
    const int Win = 256, Wout = 128;
    int bc = blockIdx.z;               // b*128 + c
    int c  = bc & 127;
    int tx = threadIdx.x;              // 32 threads x 4 outputs
    int oy = blockIdx.x * blockDim.y + threadIdx.y;

    const float* ip = in + (size_t)bc * 65536;

    float w0 = w[c*9+0], w1 = w[c*9+1], w2 = w[c*9+2];
    float w3 = w[c*9+3], w4 = w[c*9+4], w5 = w[c*9+5];
    float w6 = w[c*9+6], w7 = w[c*9+7], w8 = w[c*9+8];
    float inv  = gamma[c] * rsqrtf(var[c] + EPSV);
    float bias = beta[c] - mean[c] * inv;
    float a    = alpha[c];

    int iy = 2 * oy;
    float f0[9], f1[9], f2[9];
    if (oy > 0) load_row9(f0, ip + (size_t)(iy - 1) * Win, tx);
    else {
#pragma unroll
        for (int i = 0; i < 9; ++i) f0[i] = 0.f;
    }
    load_row9(f1, ip + (size_t)iy * Win, tx);
    load_row9(f2, ip + (size_t)(iy + 1) * Win, tx);

    float res[4];
#pragma unroll
    for (int j = 0; j < 4; ++j) {
        float s = w0 * f0[2*j] + w1 * f0[2*j+1] + w2 * f0[2*j+2]
                + w3 * f1[2*j] + w4 * f1[2*j+1] + w5 * f1[2*j+2]
                + w6 * f2[2*j] + w7 * f2[2*j+1] + w8 * f2[2*j+2];
        float y = s * inv + bias;
        res[j] = (y > 0.f) ? y : a * y;
    }
    __half2 h0 = __floats2half2_rn(res[0], res[1]);
    __half2 h1 = __floats2half2_rn(res[2], res[3]);
    __half* op = out + (size_t)bc * 16384 + (size_t)oy * Wout + tx * 4;
    *(__half2*)op       = h0;
    *(__half2*)(op + 2) = h1;
}

// ---------------- kernel 2: dwconv s2 + BN + PReLU, fp16 in -> fp16 out ----------------
__device__ __forceinline__ void load_row9h(float* f, const __half* rowp, int tx)
{
    if (tx > 0) {
        __half2 pv = *(const __half2*)(rowp + tx * 8 - 2);
        f[0] = __half2float(__high2half(pv));
    } else f[0] = 0.f;
    uint4 B = *(const uint4*)(rowp + tx * 8);
    const __half2* hb = (const __half2*)&B;
#pragma unroll
    for (int i = 0; i < 4; ++i) {
        float2 v = __half22float2(hb[i]);
        f[1 + 2*i] = v.x;
        f[2 + 2*i] = v.y;
    }
}

__global__ void dwconv2_kernel(
    const __half* __restrict__ in, __half* __restrict__ out,
    const float* __restrict__ w,
    const float* __restrict__ gamma, const float* __restrict__ beta,
    const float* __restrict__ mean, const float* __restrict__ var,
    const float* __restrict__ alpha)
{
    const int Win = 128, Wout = 64;
    int bc = blockIdx.z;
    int c  = bc & 127;
    int tx = threadIdx.x;              // 16 threads x 4 outputs
    int oy = blockIdx.x * blockDim.y + threadIdx.y;

    const __half* ip = in + (size_t)bc * 16384;

    float w0 = w[c*9+0], w1 = w[c*9+1], w2 = w[c*9+2];
    float w3 = w[c*9+3], w4 = w[c*9+4], w5 = w[c*9+5];
    float w6 = w[c*9+6], w7 = w[c*9+7], w8 = w[c*9+8];
    float inv  = gamma[c] * rsqrtf(var[c] + EPSV);
    float bias = beta[c] - mean[c] * inv;
    float a    = alpha[c];

    int iy = 2 * oy;
    float f0[9], f1[9], f2[9];
    if (oy > 0) load_row9h(f0, ip + (size_t)(iy - 1) * Win, tx);
    else {
#pragma unroll
        for (int i = 0; i < 9; ++i) f0[i] = 0.f;
    }
    load_row9h(f1, ip + (size_t)iy * Win, tx);
    load_row9h(f2, ip + (size_t)(iy + 1) * Win, tx);

    float res[4];
#pragma unroll
    for (int j = 0; j < 4; ++j) {
        float s = w0 * f0[2*j] + w1 * f0[2*j+1] + w2 * f0[2*j+2]
                + w3 * f1[2*j] + w4 * f1[2*j+1] + w5 * f1[2*j+2]
                + w6 * f2[2*j] + w7 * f2[2*j+1] + w8 * f2[2*j+2];
        float y = s * inv + bias;
        res[j] = (y > 0.f) ? y : a * y;
    }
    __half2 h0 = __floats2half2_rn(res[0], res[1]);
    __half2 h1 = __floats2half2_rn(res[2], res[3]);
    __half* op = out + (size_t)bc * 4096 + (size_t)oy * Wout + tx * 4;
    *(__half2*)op       = h0;
    *(__half2*)(op + 2) = h1;
}

// ---------------- common MMA helpers ----------------
__device__ __forceinline__ unsigned smem_u32(const void* p) {
    return (unsigned)__cvta_generic_to_shared(p);
}

#define LDSM_X4(r, addr) \
    asm volatile("ldmatrix.sync.aligned.m8n8.x4.shared.b16 {%0,%1,%2,%3},[%4];" \
        : "=r"((r)[0]), "=r"((r)[1]), "=r"((r)[2]), "=r"((r)[3]) : "r"(addr))

#define LDSM_X4_T(r, addr) \
    asm volatile("ldmatrix.sync.aligned.m8n8.x4.trans.shared.b16 {%0,%1,%2,%3},[%4];" \
        : "=r"((r)[0]), "=r"((r)[1]), "=r"((r)[2]), "=r"((r)[3]) : "r"(addr))

#define MMAF16(C, A, b0, b1) \
    asm volatile("mma.sync.aligned.m16n8k16.row.col.f32.f16.f16.f32 " \
        "{%0,%1,%2,%3},{%4,%5,%6,%7},{%8,%9},{%0,%1,%2,%3};" \
        : "+f"((C)[0]), "+f"((C)[1]), "+f"((C)[2]), "+f"((C)[3]) \
        : "r"((A)[0]), "r"((A)[1]), "r"((A)[2]), "r"((A)[3]), "r"(b0), "r"(b1))

#define CP_ASYNC16(dst, src) \
    asm volatile("cp.async.cg.shared.global [%0],[%1],16;" :: "r"(dst), "l"(src))
#define CP_COMMIT() asm volatile("cp.async.commit_group;")
#define CP_WAIT0()  asm volatile("cp.async.wait_group 0;" ::: "memory")

// ---------------- kernel 3: gram partials via fp16 MMA + fused last-CTA softmax ------
#define LDP 264

__global__ __launch_bounds__(256) void gram_mma_kernel()
{
    extern __shared__ __half P[];       // [128 c][LDP]
    int s = blockIdx.x, b = blockIdx.y;
    int tid = threadIdx.x, warp = tid >> 5, lane = tid & 31;

    const __half* src = g_p2h + (size_t)b * 524288 + s * 256;
#pragma unroll
    for (int i = 0; i < 16; ++i) {
        int idx = i * 256 + tid;
        int c = idx >> 5, j = idx & 31;
        *(uint4*)(P + c * LDP + j * 8) = *(const uint4*)(src + (size_t)c * 4096 + j * 8);
    }
    __syncthreads();

    int i0 = (warp >> 1) * 32;
    int j0 = (warp & 1) * 64;
    int r  = lane & 15, q = lane >> 4;
    int br = (lane & 7) | ((lane >> 4) << 3);
    int bq = (lane >> 3) & 1;

    float acc[2][8][4];
#pragma unroll
    for (int mf = 0; mf < 2; ++mf)
#pragma unroll
        for (int nf = 0; nf < 8; ++nf)
#pragma unroll
            for (int e = 0; e < 4; ++e) acc[mf][nf][e] = 0.f;

#pragma unroll
    for (int ks = 0; ks < 16; ++ks) {
        int k0 = ks * 16;
        unsigned ah[2][4];
#pragma unroll
        for (int mf = 0; mf < 2; ++mf)
            LDSM_X4(ah[mf], smem_u32(P + (i0 + mf * 16 + r) * LDP + k0 + q * 8));
#pragma unroll
        for (int nc = 0; nc < 4; ++nc) {
            unsigned bf[4];
            LDSM_X4(bf, smem_u32(P + (j0 + nc * 16 + br) * LDP + k0 + bq * 8));
#pragma unroll
            for (int mf = 0; mf < 2; ++mf) {
                MMAF16(acc[mf][nc * 2],     ah[mf], bf[0], bf[1]);
                MMAF16(acc[mf][nc * 2 + 1], ah[mf], bf[2], bf[3]);
            }
        }
    }

    float* dst = g_part + ((size_t)b * 16 + s) * 16384;
    int rbase = i0 + (lane >> 2);
    int cbase = j0 + ((lane & 3) << 1);
#pragma unroll
    for (int mf = 0; mf < 2; ++mf) {
#pragma unroll
        for (int nf = 0; nf < 8; ++nf) {
            float* p0 = dst + (size_t)(rbase + mf * 16) * 128 + cbase + nf * 8;
            float* p1 = p0 + 8 * 128;
            *(float2*)p0 = make_float2(acc[mf][nf][0], acc[mf][nf][1]);
            *(float2*)p1 = make_float2(acc[mf][nf][2], acc[mf][nf][3]);
        }
    }

    // ---- last-CTA-per-batch fused softmax (partials are L2-hot) ----
    __shared__ int isLast;
    __threadfence();                    // make this CTA's partial stores visible
    if (tid == 0) {
        int v = atomicAdd(&g_cnt[b], 1);
        isLast = (v == 15);
    }
    __syncthreads();
    if (!isLast) return;
    __threadfence();                    // order reads after all arrivals

    for (int i = warp; i < 128; i += 8) {      // row k = i
        const float* p = g_part + (size_t)b * 262144 + (size_t)i * 128 + lane * 4;
        float4 g = make_float4(0.f, 0.f, 0.f, 0.f);
#pragma unroll
        for (int t = 0; t < 16; ++t) {
            float4 v = *(const float4*)(p + (size_t)t * 16384);
            g.x += v.x; g.y += v.y; g.z += v.z; g.w += v.w;
        }
        const float sc = 1.0f / 64.0f;  // (64*64)^-0.5
        g.x *= sc; g.y *= sc; g.z *= sc; g.w *= sc;

        float m = fmaxf(fmaxf(g.x, g.y), fmaxf(g.z, g.w));
#pragma unroll
        for (int off = 16; off; off >>= 1)
            m = fmaxf(m, __shfl_xor_sync(0xFFFFFFFFu, m, off));

        float e0 = __expf(g.x - m), e1 = __expf(g.y - m);
        float e2 = __expf(g.z - m), e3 = __expf(g.w - m);
        float sum = e0 + e1 + e2 + e3;
#pragma unroll
        for (int off = 16; off; off >>= 1)
            sum += __shfl_xor_sync(0xFFFFFFFFu, sum, off);
        float inv = 1.0f / sum;

        // transposed fp16 store: g_Sth[b][c][k=i], c = lane*4 + e
        __half* dsth = g_Sth + (size_t)b * 16384 + (size_t)(lane * 4) * 128 + i;
        dsth[0]   = __float2half_rn(e0 * inv);
        dsth[128] = __float2half_rn(e1 * inv);
        dsth[256] = __float2half_rn(e2 * inv);
        dsth[384] = __float2half_rn(e3 * inv);
    }

    __syncthreads();
    if (tid == 0) g_cnt[b] = 0;         // self-reset for graph replay
}

// ---------------- kernel 5: attention einsum, fp16 MMA ----------------
#define LDA 136
#define LDB 72
#define TN  64
#define NSUB 8

#define ATTN_SMEM 104448

__global__ __launch_bounds__(256, 2) void attn_mma_kernel(const float* __restrict__ x,
                                                          float* __restrict__ out)
{
    extern __shared__ char smraw[];
    __half* Ahi = (__half*)smraw;              // [128 c][LDA k]
    __half* B0  = Ahi + 128 * LDA;             // [128 k][LDB n], double buffered
    __half* B1  = B0 + 128 * LDB;
    float*  Xs  = (float*)(B1 + 128 * LDB);    // staging [128 k][64 n] fp32

    int b    = blockIdx.y;
    int tid  = threadIdx.x;
    int warp = tid >> 5, lane = tid & 31;

    const float* xb = x + (size_t)b * 128 * 65536;
    float*       ob = out + (size_t)b * 128 * 65536;

    {
        int n0 = blockIdx.x * (NSUB * TN);
#pragma unroll
        for (int i = 0; i < 8; ++i) {
            int idx = i * 256 + tid;
            int k = idx >> 4, c4 = idx & 15;
            CP_ASYNC16(smem_u32(Xs + k * TN + c4 * 4),
                       xb + (size_t)k * 65536 + n0 + c4 * 4);
        }
        CP_COMMIT();
    }

    // ---- A prep: copy fp16 sim directly (no conversion)
    {
        const __half* Sp = g_Sth + (size_t)b * 16384;
#pragma unroll
        for (int i = 0; i < 8; ++i) {
            int idx = i * 256 + tid;
            int c = idx >> 4, k8 = (idx & 15) * 8;
            *(uint4*)(Ahi + c * LDA + k8) = *(const uint4*)(Sp + c * 128 + k8);
        }
    }

    int mw = (warp >> 1) * 32;
    int nw = (warp & 1) * 32;
    int r  = lane & 15, q = lane >> 4;

    for (int t = 0; t < NSUB; ++t) {
        __half* Bp = (t & 1) ? B1 : B0;
        int n0 = (blockIdx.x * NSUB + t) * TN;

        CP_WAIT0();
#pragma unroll
        for (int i = 0; i < 8; ++i) {
            int idx = i * 256 + tid;
            int k = idx >> 4, c4 = idx & 15;
            float4 v = *(const float4*)(Xs + k * TN + c4 * 4);
            __half* ph = Bp + k * LDB + c4 * 4;
            *(__half2*)(ph)     = __floats2half2_rn(v.x, v.y);
            *(__half2*)(ph + 2) = __floats2half2_rn(v.z, v.w);
        }

        if (t + 1 < NSUB) {
            int n0n = n0 + TN;
#pragma unroll
            for (int i = 0; i < 8; ++i) {
                int idx = i * 256 + tid;
                int k = idx >> 4, c4 = idx & 15;
                CP_ASYNC16(smem_u32(Xs + k * TN + c4 * 4),
                           xb + (size_t)k * 65536 + n0n + c4 * 4);
            }
            CP_COMMIT();
        }

        __syncthreads();

        float acc[2][4][4];
#pragma unroll
        for (int mf = 0; mf < 2; ++mf)
#pragma unroll
            for (int nf = 0; nf < 4; ++nf)
#pragma unroll
                for (int e = 0; e < 4; ++e) acc[mf][nf][e] = 0.f;

#pragma unroll
        for (int ks = 0; ks < 8; ++ks) {
            int k0 = ks * 16;
            unsigned ah[2][4];
#pragma unroll
            for (int mf = 0; mf < 2; ++mf)
                LDSM_X4(ah[mf], smem_u32(Ahi + (mw + mf * 16 + r) * LDA + k0 + q * 8));
#pragma unroll
            for (int nc = 0; nc < 2; ++nc) {
                unsigned bf[4];
                LDSM_X4_T(bf, smem_u32(Bp + (k0 + r) * LDB + nw + nc * 16 + q * 8));
#pragma unroll
                for (int mf = 0; mf < 2; ++mf) {
#pragma unroll
                    for (int h = 0; h < 2; ++h) {
                        float* C = acc[mf][nc * 2 + h];
                        MMAF16(C, ah[mf], bf[2 * h], bf[2 * h + 1]);
                    }
                }
            }
        }

        int rbase = mw + (lane >> 2);
        int cbase = nw + ((lane & 3) << 1);
#pragma unroll
        for (int mf = 0; mf < 2; ++mf) {
#pragma unroll
            for (int nf = 0; nf < 4; ++nf) {
                float* p0 = ob + (size_t)(rbase + mf * 16) * 65536 + n0 + cbase + nf * 8;
                float* p1 = p0 + 8ull * 65536;
                *(float2*)p0 = make_float2(acc[mf][nf][0], acc[mf][nf][1]);
                *(float2*)p1 = make_float2(acc[mf][nf][2], acc[mf][nf][3]);
            }
        }
    }
}

// ---------------- launch: single-stream sequence ----------------
extern "C" void kernel_launch(void* const* d_in, const int* in_sizes, int n_in,
                              void* d_out, int out_size)
{
    (void)in_sizes; (void)n_in; (void)out_size;
    const float* x    = (const float*)d_in[0];
    const float* c1w  = (const float*)d_in[1];
    const float* g1   = (const float*)d_in[2];
    const float* b1   = (const float*)d_in[3];
    const float* m1   = (const float*)d_in[4];
    const float* v1   = (const float*)d_in[5];
    const float* a1   = (const float*)d_in[6];
    const float* c2w  = (const float*)d_in[7];
    const float* g2   = (const float*)d_in[8];
    const float* b2   = (const float*)d_in[9];
    const float* m2   = (const float*)d_in[10];
    const float* v2   = (const float*)d_in[11];
    const float* a2   = (const float*)d_in[12];
    float* out = (float*)d_out;

    void* tmp;
    cudaGetSymbolAddress(&tmp, g_p1h);  __half* p1 = (__half*)tmp;
    cudaGetSymbolAddress(&tmp, g_p2h);  __half* p2 = (__half*)tmp;

    cudaFuncSetAttribute(gram_mma_kernel,
                         cudaFuncAttributeMaxDynamicSharedMemorySize, 128 * LDP * 2);
    cudaFuncSetAttribute(attn_mma_kernel,
                         cudaFuncAttributeMaxDynamicSharedMemorySize, ATTN_SMEM);

    dwconv1_kernel<<<dim3(16, 1, 1024), dim3(32, 8)>>>(x, p1, c1w, g1, b1, m1, v1, a1);
    dwconv2_kernel<<<dim3(4, 1, 1024), dim3(16, 16)>>>(p1, p2, c2w, g2, b2, m2, v2, a2);
    gram_mma_kernel<<<dim3(16, 8), 256, 128 * LDP * 2>>>();
    attn_mma_kernel<<<dim3(128, 8), 256, ATTN_SMEM>>>(x, out);
}

// round 17
// speedup vs baseline: 1.1417x; 1.1417x over previous
#include <cuda_runtime.h>
#include <cuda_fp16.h>
#include <cstdint>

#define EPSV 1e-5f

// ---------------- scratch (device globals; no allocation allowed) ----------------
__device__ __half g_p1h[8ull * 128 * 128 * 128];  // pooled stage 1 fp16: (B,C,128,128)
__device__ __half g_p2h[8ull * 128 * 64 * 64];    // pooled stage 2 fp16: (B,C,4096)
__device__ float  g_part[8ull * 16 * 128 * 128];  // gram partials: (B, 16 splits, C, C)
__device__ __half g_Sth[8ull * 128 * 128];        // sim transposed fp16: [b][c][k]

// ---------------- kernel 1: dwconv s2 + BN + PReLU, fp32 in -> fp16 out ----------------
__device__ __forceinline__ void load_row9(float* f, const float* rowp, int tx)
{
    float4 A = (tx > 0) ? *(const float4*)(rowp + tx * 8 - 4)
                        : make_float4(0.f, 0.f, 0.f, 0.f);
    float4 B = *(const float4*)(rowp + tx * 8);
    float4 C = *(const float4*)(rowp + tx * 8 + 4);
    f[0] = A.w;
    f[1] = B.x; f[2] = B.y; f[3] = B.z; f[4] = B.w;
    f[5] = C.x; f[6] = C.y; f[7] = C.z; f[8] = C.w;
}

__global__ void dwconv1_kernel(
    const float* __restrict__ in, __half* __restrict__ out,
    const float* __restrict__ w,
    const float* __restrict__ gamma, const float* __restrict__ beta,
    const float* __restrict__ mean, const float* __restrict__ var,
    const float* __restrict__ alpha)
{
    const int Win = 256, Wout = 128;
    int bc = blockIdx.z;               // b*128 + c
    int c  = bc & 127;
    int tx = threadIdx.x;              // 32 threads x 4 outputs
    int oy = blockIdx.x * blockDim.y + threadIdx.y;

    const float* ip = in + (size_t)bc * 65536;

    float w0 = w[c*9+0], w1 = w[c*9+1], w2 = w[c*9+2];
    float w3 = w[c*9+3], w4 = w[c*9+4], w5 = w[c*9+5];
    float w6 = w[c*9+6], w7 = w[c*9+7], w8 = w[c*9+8];
    float inv  = gamma[c] * rsqrtf(var[c] + EPSV);
    float bias = beta[c] - mean[c] * inv;
    float a    = alpha[c];

    int iy = 2 * oy;
    float f0[9], f1[9], f2[9];
    if (oy > 0) load_row9(f0, ip + (size_t)(iy - 1) * Win, tx);
    else {
#pragma unroll
        for (int i = 0; i < 9; ++i) f0[i] = 0.f;
    }
    load_row9(f1, ip + (size_t)iy * Win, tx);
    load_row9(f2, ip + (size_t)(iy + 1) * Win, tx);

    float res[4];
#pragma unroll
    for (int j = 0; j < 4; ++j) {
        float s = w0 * f0[2*j] + w1 * f0[2*j+1] + w2 * f0[2*j+2]
                + w3 * f1[2*j] + w4 * f1[2*j+1] + w5 * f1[2*j+2]
                + w6 * f2[2*j] + w7 * f2[2*j+1] + w8 * f2[2*j+2];
        float y = s * inv + bias;
        res[j] = (y > 0.f) ? y : a * y;
    }
    __half2 h0 = __floats2half2_rn(res[0], res[1]);
    __half2 h1 = __floats2half2_rn(res[2], res[3]);
    __half* op = out + (size_t)bc * 16384 + (size_t)oy * Wout + tx * 4;
    *(__half2*)op       = h0;
    *(__half2*)(op + 2) = h1;
}

// ---------------- kernel 2: dwconv s2 + BN + PReLU, fp16 in -> fp16 out ----------------
__device__ __forceinline__ void load_row9h(float* f, const __half* rowp, int tx)
{
    if (tx > 0) {
        __half2 pv = *(const __half2*)(rowp + tx * 8 - 2);
        f[0] = __half2float(__high2half(pv));
    } else f[0] = 0.f;
    uint4 B = *(const uint4*)(rowp + tx * 8);
    const __half2* hb = (const __half2*)&B;
#pragma unroll
    for (int i = 0; i < 4; ++i) {
        float2 v = __half22float2(hb[i]);
        f[1 + 2*i] = v.x;
        f[2 + 2*i] = v.y;
    }
}

__global__ void dwconv2_kernel(
    const __half* __restrict__ in, __half* __restrict__ out,
    const float* __restrict__ w,
    const float* __restrict__ gamma, const float* __restrict__ beta,
    const float* __restrict__ mean, const float* __restrict__ var,
    const float* __restrict__ alpha)
{
    const int Win = 128, Wout = 64;
    int bc = blockIdx.z;
    int c  = bc & 127;
    int tx = threadIdx.x;              // 16 threads x 4 outputs
    int oy = blockIdx.x * blockDim.y + threadIdx.y;

    const __half* ip = in + (size_t)bc * 16384;

    float w0 = w[c*9+0], w1 = w[c*9+1], w2 = w[c*9+2];
    float w3 = w[c*9+3], w4 = w[c*9+4], w5 = w[c*9+5];
    float w6 = w[c*9+6], w7 = w[c*9+7], w8 = w[c*9+8];
    float inv  = gamma[c] * rsqrtf(var[c] + EPSV);
    float bias = beta[c] - mean[c] * inv;
    float a    = alpha[c];

    int iy = 2 * oy;
    float f0[9], f1[9], f2[9];
    if (oy > 0) load_row9h(f0, ip + (size_t)(iy - 1) * Win, tx);
    else {
#pragma unroll
        for (int i = 0; i < 9; ++i) f0[i] = 0.f;
    }
    load_row9h(f1, ip + (size_t)iy * Win, tx);
    load_row9h(f2, ip + (size_t)(iy + 1) * Win, tx);

    float res[4];
#pragma unroll
    for (int j = 0; j < 4; ++j) {
        float s = w0 * f0[2*j] + w1 * f0[2*j+1] + w2 * f0[2*j+2]
                + w3 * f1[2*j] + w4 * f1[2*j+1] + w5 * f1[2*j+2]
                + w6 * f2[2*j] + w7 * f2[2*j+1] + w8 * f2[2*j+2];
        float y = s * inv + bias;
        res[j] = (y > 0.f) ? y : a * y;
    }
    __half2 h0 = __floats2half2_rn(res[0], res[1]);
    __half2 h1 = __floats2half2_rn(res[2], res[3]);
    __half* op = out + (size_t)bc * 4096 + (size_t)oy * Wout + tx * 4;
    *(__half2*)op       = h0;
    *(__half2*)(op + 2) = h1;
}

// ---------------- common MMA helpers ----------------
__device__ __forceinline__ unsigned smem_u32(const void* p) {
    return (unsigned)__cvta_generic_to_shared(p);
}

#define LDSM_X4(r, addr) \
    asm volatile("ldmatrix.sync.aligned.m8n8.x4.shared.b16 {%0,%1,%2,%3},[%4];" \
        : "=r"((r)[0]), "=r"((r)[1]), "=r"((r)[2]), "=r"((r)[3]) : "r"(addr))

#define LDSM_X4_T(r, addr) \
    asm volatile("ldmatrix.sync.aligned.m8n8.x4.trans.shared.b16 {%0,%1,%2,%3},[%4];" \
        : "=r"((r)[0]), "=r"((r)[1]), "=r"((r)[2]), "=r"((r)[3]) : "r"(addr))

#define MMAF16(C, A, b0, b1) \
    asm volatile("mma.sync.aligned.m16n8k16.row.col.f32.f16.f16.f32 " \
        "{%0,%1,%2,%3},{%4,%5,%6,%7},{%8,%9},{%0,%1,%2,%3};" \
        : "+f"((C)[0]), "+f"((C)[1]), "+f"((C)[2]), "+f"((C)[3]) \
        : "r"((A)[0]), "r"((A)[1]), "r"((A)[2]), "r"((A)[3]), "r"(b0), "r"(b1))

#define CP_ASYNC16(dst, src) \
    asm volatile("cp.async.cg.shared.global [%0],[%1],16;" :: "r"(dst), "l"(src))
#define CP_COMMIT() asm volatile("cp.async.commit_group;")
#define CP_WAIT0()  asm volatile("cp.async.wait_group 0;" ::: "memory")

// ---------------- kernel 3: gram partials via fp16 MMA ----------------
#define LDP 264

__global__ __launch_bounds__(256) void gram_mma_kernel()
{
    extern __shared__ __half P[];       // [128 c][LDP]
    int s = blockIdx.x, b = blockIdx.y;
    int tid = threadIdx.x, warp = tid >> 5, lane = tid & 31;

    const __half* src = g_p2h + (size_t)b * 524288 + s * 256;
#pragma unroll
    for (int i = 0; i < 16; ++i) {
        int idx = i * 256 + tid;
        int c = idx >> 5, j = idx & 31;
        *(uint4*)(P + c * LDP + j * 8) = *(const uint4*)(src + (size_t)c * 4096 + j * 8);
    }
    __syncthreads();

    int i0 = (warp >> 1) * 32;
    int j0 = (warp & 1) * 64;
    int r  = lane & 15, q = lane >> 4;
    int br = (lane & 7) | ((lane >> 4) << 3);
    int bq = (lane >> 3) & 1;

    float acc[2][8][4];
#pragma unroll
    for (int mf = 0; mf < 2; ++mf)
#pragma unroll
        for (int nf = 0; nf < 8; ++nf)
#pragma unroll
            for (int e = 0; e < 4; ++e) acc[mf][nf][e] = 0.f;

#pragma unroll
    for (int ks = 0; ks < 16; ++ks) {
        int k0 = ks * 16;
        unsigned ah[2][4];
#pragma unroll
        for (int mf = 0; mf < 2; ++mf)
            LDSM_X4(ah[mf], smem_u32(P + (i0 + mf * 16 + r) * LDP + k0 + q * 8));
#pragma unroll
        for (int nc = 0; nc < 4; ++nc) {
            unsigned bf[4];
            LDSM_X4(bf, smem_u32(P + (j0 + nc * 16 + br) * LDP + k0 + bq * 8));
#pragma unroll
            for (int mf = 0; mf < 2; ++mf) {
                MMAF16(acc[mf][nc * 2],     ah[mf], bf[0], bf[1]);
                MMAF16(acc[mf][nc * 2 + 1], ah[mf], bf[2], bf[3]);
            }
        }
    }

    float* dst = g_part + ((size_t)b * 16 + s) * 16384;
    int rbase = i0 + (lane >> 2);
    int cbase = j0 + ((lane & 3) << 1);
#pragma unroll
    for (int mf = 0; mf < 2; ++mf) {
#pragma unroll
        for (int nf = 0; nf < 8; ++nf) {
            float* p0 = dst + (size_t)(rbase + mf * 16) * 128 + cbase + nf * 8;
            float* p1 = p0 + 8 * 128;
            *(float2*)p0 = make_float2(acc[mf][nf][0], acc[mf][nf][1]);
            *(float2*)p1 = make_float2(acc[mf][nf][2], acc[mf][nf][3]);
        }
    }
}

// ---------------- kernel 4: warp-per-row softmax -> fp16 transposed sim ----------
// grid (16, 8), 256 threads = 8 warps; warp w handles row i = blockIdx.x*8 + w.
__global__ __launch_bounds__(256) void softmax_kernel()
{
    int wid = threadIdx.x >> 5, lane = threadIdx.x & 31;
    int i = blockIdx.x * 8 + wid;      // row k
    int b = blockIdx.y;

    const float* p = g_part + (size_t)b * 262144 + (size_t)i * 128 + lane * 4;
    float4 g = make_float4(0.f, 0.f, 0.f, 0.f);
#pragma unroll
    for (int s = 0; s < 16; ++s) {
        float4 v = *(const float4*)(p + (size_t)s * 16384);
        g.x += v.x; g.y += v.y; g.z += v.z; g.w += v.w;
    }
    const float sc = 1.0f / 64.0f;     // (64*64)^-0.5
    g.x *= sc; g.y *= sc; g.z *= sc; g.w *= sc;

    float m = fmaxf(fmaxf(g.x, g.y), fmaxf(g.z, g.w));
#pragma unroll
    for (int off = 16; off; off >>= 1)
        m = fmaxf(m, __shfl_xor_sync(0xFFFFFFFFu, m, off));

    float e0 = __expf(g.x - m), e1 = __expf(g.y - m);
    float e2 = __expf(g.z - m), e3 = __expf(g.w - m);
    float s = e0 + e1 + e2 + e3;
#pragma unroll
    for (int off = 16; off; off >>= 1)
        s += __shfl_xor_sync(0xFFFFFFFFu, s, off);
    float inv = 1.0f / s;

    // transposed fp16 store: g_Sth[b][c][k=i], c = lane*4 + e
    __half* dst = g_Sth + (size_t)b * 16384 + (size_t)(lane * 4) * 128 + i;
    dst[0]   = __float2half_rn(e0 * inv);
    dst[128] = __float2half_rn(e1 * inv);
    dst[256] = __float2half_rn(e2 * inv);
    dst[384] = __float2half_rn(e3 * inv);
}

// ---------------- kernel 5: attention einsum, fp16 MMA ----------------
#define LDA 136
#define LDB 72
#define TN  64
#define NSUB 8

#define ATTN_SMEM 104448

__global__ __launch_bounds__(256, 2) void attn_mma_kernel(const float* __restrict__ x,
                                                          float* __restrict__ out)
{
    extern __shared__ char smraw[];
    __half* Ahi = (__half*)smraw;              // [128 c][LDA k]
    __half* B0  = Ahi + 128 * LDA;             // [128 k][LDB n], double buffered
    __half* B1  = B0 + 128 * LDB;
    float*  Xs  = (float*)(B1 + 128 * LDB);    // staging [128 k][64 n] fp32

    int b    = blockIdx.y;
    int tid  = threadIdx.x;
    int warp = tid >> 5, lane = tid & 31;

    const float* xb = x + (size_t)b * 128 * 65536;
    float*       ob = out + (size_t)b * 128 * 65536;

    {
        int n0 = blockIdx.x * (NSUB * TN);
#pragma unroll
        for (int i = 0; i < 8; ++i) {
            int idx = i * 256 + tid;
            int k = idx >> 4, c4 = idx & 15;
            CP_ASYNC16(smem_u32(Xs + k * TN + c4 * 4),
                       xb + (size_t)k * 65536 + n0 + c4 * 4);
        }
        CP_COMMIT();
    }

    // ---- A prep: copy fp16 sim directly (no conversion)
    {
        const __half* Sp = g_Sth + (size_t)b * 16384;
#pragma unroll
        for (int i = 0; i < 8; ++i) {
            int idx = i * 256 + tid;
            int c = idx >> 4, k8 = (idx & 15) * 8;
            *(uint4*)(Ahi + c * LDA + k8) = *(const uint4*)(Sp + c * 128 + k8);
        }
    }

    int mw = (warp >> 1) * 32;
    int nw = (warp & 1) * 32;
    int r  = lane & 15, q = lane >> 4;

    for (int t = 0; t < NSUB; ++t) {
        __half* Bp = (t & 1) ? B1 : B0;
        int n0 = (blockIdx.x * NSUB + t) * TN;

        CP_WAIT0();
#pragma unroll
        for (int i = 0; i < 8; ++i) {
            int idx = i * 256 + tid;
            int k = idx >> 4, c4 = idx & 15;
            float4 v = *(const float4*)(Xs + k * TN + c4 * 4);
            __half* ph = Bp + k * LDB + c4 * 4;
            *(__half2*)(ph)     = __floats2half2_rn(v.x, v.y);
            *(__half2*)(ph + 2) = __floats2half2_rn(v.z, v.w);
        }

        if (t + 1 < NSUB) {
            int n0n = n0 + TN;
#pragma unroll
            for (int i = 0; i < 8; ++i) {
                int idx = i * 256 + tid;
                int k = idx >> 4, c4 = idx & 15;
                CP_ASYNC16(smem_u32(Xs + k * TN + c4 * 4),
                           xb + (size_t)k * 65536 + n0n + c4 * 4);
            }
            CP_COMMIT();
        }

        __syncthreads();

        float acc[2][4][4];
#pragma unroll
        for (int mf = 0; mf < 2; ++mf)
#pragma unroll
            for (int nf = 0; nf < 4; ++nf)
#pragma unroll
                for (int e = 0; e < 4; ++e) acc[mf][nf][e] = 0.f;

#pragma unroll
        for (int ks = 0; ks < 8; ++ks) {
            int k0 = ks * 16;
            unsigned ah[2][4];
#pragma unroll
            for (int mf = 0; mf < 2; ++mf)
                LDSM_X4(ah[mf], smem_u32(Ahi + (mw + mf * 16 + r) * LDA + k0 + q * 8));
#pragma unroll
            for (int nc = 0; nc < 2; ++nc) {
                unsigned bf[4];
                LDSM_X4_T(bf, smem_u32(Bp + (k0 + r) * LDB + nw + nc * 16 + q * 8));
#pragma unroll
                for (int mf = 0; mf < 2; ++mf) {
#pragma unroll
                    for (int h = 0; h < 2; ++h) {
                        float* C = acc[mf][nc * 2 + h];
                        MMAF16(C, ah[mf], bf[2 * h], bf[2 * h + 1]);
                    }
                }
            }
        }

        int rbase = mw + (lane >> 2);
        int cbase = nw + ((lane & 3) << 1);
#pragma unroll
        for (int mf = 0; mf < 2; ++mf) {
#pragma unroll
            for (int nf = 0; nf < 4; ++nf) {
                float* p0 = ob + (size_t)(rbase + mf * 16) * 65536 + n0 + cbase + nf * 8;
                float* p1 = p0 + 8ull * 65536;
                *(float2*)p0 = make_float2(acc[mf][nf][0], acc[mf][nf][1]);
                *(float2*)p1 = make_float2(acc[mf][nf][2], acc[mf][nf][3]);
            }
        }
    }
}

// ---------------- launch: single-stream sequence ----------------
extern "C" void kernel_launch(void* const* d_in, const int* in_sizes, int n_in,
                              void* d_out, int out_size)
{
    (void)in_sizes; (void)n_in; (void)out_size;
    const float* x    = (const float*)d_in[0];
    const float* c1w  = (const float*)d_in[1];
    const float* g1   = (const float*)d_in[2];
    const float* b1   = (const float*)d_in[3];
    const float* m1   = (const float*)d_in[4];
    const float* v1   = (const float*)d_in[5];
    const float* a1   = (const float*)d_in[6];
    const float* c2w  = (const float*)d_in[7];
    const float* g2   = (const float*)d_in[8];
    const float* b2   = (const float*)d_in[9];
    const float* m2   = (const float*)d_in[10];
    const float* v2   = (const float*)d_in[11];
    const float* a2   = (const float*)d_in[12];
    float* out = (float*)d_out;

    void* tmp;
    cudaGetSymbolAddress(&tmp, g_p1h);  __half* p1 = (__half*)tmp;
    cudaGetSymbolAddress(&tmp, g_p2h);  __half* p2 = (__half*)tmp;

    cudaFuncSetAttribute(gram_mma_kernel,
                         cudaFuncAttributeMaxDynamicSharedMemorySize, 128 * LDP * 2);
    cudaFuncSetAttribute(attn_mma_kernel,
                         cudaFuncAttributeMaxDynamicSharedMemorySize, ATTN_SMEM);

    dwconv1_kernel<<<dim3(16, 1, 1024), dim3(32, 8)>>>(x, p1, c1w, g1, b1, m1, v1, a1);
    dwconv2_kernel<<<dim3(4, 1, 1024), dim3(16, 16)>>>(p1, p2, c2w, g2, b2, m2, v2, a2);
    gram_mma_kernel<<<dim3(16, 8), 256, 128 * LDP * 2>>>();
    softmax_kernel<<<dim3(16, 8), 256>>>();
    attn_mma_kernel<<<dim3(128, 8), 256, ATTN_SMEM>>>(x, out);
}